// round 3
// baseline (speedup 1.0000x reference)
#include <cuda_runtime.h>
#include <cuda_bf16.h>
#include <cstdint>

#define D_FEAT 32

// ---------------------------------------------------------------------------
// out[n,:] = x[n,:] * sum_{e: tgt[e]==n} W[e]
// (reference gathers AND scatters on target, so the [E,32] message matrix
// factorizes into a scalar segment-sum followed by a broadcast multiply).
// The per-node scalar accumulator lives inside d_out at out[n*32].
// ---------------------------------------------------------------------------

// Pass 0: zero the accumulator slots.
__global__ void zero_slots_kernel(float* __restrict__ out, int N)
{
    int n = blockIdx.x * blockDim.x + threadIdx.x;
    if (n < N) out[(size_t)n * D_FEAT] = 0.0f;
}

// Pass 1: scalar segment-sum of W onto target-node slots.
// edge_index is INT32 (JAX x64 disabled -> jnp.int64 request materializes
// as int32). Unsigned bounds check guards against a dtype surprise.
__global__ void accum_kernel(const int* __restrict__ tgt,
                             const float* __restrict__ W,
                             float* __restrict__ out,
                             int E, unsigned int N)
{
    int base = blockIdx.x * (blockDim.x * 4) + threadIdx.x;
    int stride = blockDim.x;

    #pragma unroll
    for (int k = 0; k < 4; k++) {
        int e = base + k * stride;
        if (e < E) {
            unsigned int t = (unsigned int)tgt[e];
            float w = W[e];
            if (t < N) atomicAdd(&out[(size_t)t * D_FEAT], w);
        }
    }
}

// Pass 2: out[n,:] = x[n,:] * s, s = out[n*32].
// 8 threads per node, one float4 each; all 8 lanes of a node are in the
// same warp (8 | 32, n_vec % 32 == 0), so __syncwarp() orders the scalar
// read before the lane covering slot 0 overwrites it.
__global__ void mul_kernel(const float4* __restrict__ x4,
                           float4* __restrict__ out4,
                           int n_vec)  // = N * 8
{
    int i = blockIdx.x * blockDim.x + threadIdx.x;
    if (i < n_vec) {
        int node = i >> 3;
        const float* out_s = (const float*)out4;
        float s = out_s[(size_t)node * D_FEAT];
        float4 v = x4[i];
        __syncwarp();
        v.x *= s; v.y *= s; v.z *= s; v.w *= s;
        out4[i] = v;
    }
}

// Inputs (metadata order): edge_index int32 [2, E], x f32 [N, 32], W f32 [E].
// Output: f32 [N, 32].
extern "C" void kernel_launch(void* const* d_in, const int* in_sizes, int n_in,
                              void* d_out, int out_size)
{
    const int*   edge_index = (const int*)d_in[0];
    const float* x          = (const float*)d_in[1];
    const float* W          = (const float*)d_in[2];
    float*       out        = (float*)d_out;

    const int E = in_sizes[2];           // number of edges (= len(W))
    const int N = in_sizes[1] / D_FEAT;  // number of nodes

    const int* tgt = edge_index + (size_t)E;  // second row of [2, E]

    // Pass 0: zero accumulator slots
    {
        int threads = 256;
        int blocks = (N + threads - 1) / threads;
        zero_slots_kernel<<<blocks, threads>>>(out, N);
    }

    // Pass 1: segment-sum W by target into out[n*32]
    {
        int threads = 256;
        int per_block = threads * 4;
        int blocks = (E + per_block - 1) / per_block;
        accum_kernel<<<blocks, threads>>>(tgt, W, out, E, (unsigned int)N);
    }

    // Pass 2: broadcast multiply (overwrites all of out, including slots)
    {
        int n_vec = N * (D_FEAT / 4);    // N * 8 float4s
        int threads = 256;
        int blocks = (n_vec + threads - 1) / threads;
        mul_kernel<<<blocks, threads>>>((const float4*)x, (float4*)out, n_vec);
    }
}